// round 3
// baseline (speedup 1.0000x reference)
#include <cuda_runtime.h>
#include <math_constants.h>
#include <math.h>

#define HID   4096
#define NH    32
#define HD    128
#define BSZ   2
#define SEQ   2048
#define TOK   (BSZ*SEQ)      /* 4096 */
#define QKV_N (3*HID)        /* 12288 */

// ---------------- device scratch (static, allocation-free) ----------------
__device__ int   g_idx[2*TOK];                       // [0,4096): vision slots, [4096,8192): language slots, -1 = empty
__device__ float g_q[(size_t)BSZ*NH*SEQ*HD];         // [B,NH,L,HD]
__device__ float g_k[(size_t)BSZ*NH*SEQ*HD];
__device__ float g_v[(size_t)BSZ*NH*SEQ*HD];
__device__ float g_ctx[(size_t)TOK*HID];             // [B,L,H] head-major within H

// ---------------- kernel 1: routing ----------------
__global__ void route_kernel(const int* __restrict__ tt) {
    __shared__ int cnt[2];
    int tid = threadIdx.x;
    if (tid < 2) cnt[tid] = 0;
    for (int i = tid; i < 2*TOK; i += blockDim.x) g_idx[i] = -1;
    __syncthreads();
    for (int t = tid; t < TOK; t += blockDim.x) {
        int l = t & (SEQ-1);
        int vm = (l < SEQ-1) && (tt[t] == 1) && (tt[t+1] == 1);
        int p = atomicAdd(&cnt[vm ? 0 : 1], 1);
        g_idx[(vm ? 0 : TOK) + p] = t;
    }
}

// ---------------- kernel 2: routed QKV GEMM ----------------
// C[slot, o] = sum_h X[tok(slot), h] * W[o, h]; grid (QKV_N/128, 2*TOK/128)
__global__ __launch_bounds__(256) void qkv_gemm(const float* __restrict__ X,
                                                const float* __restrict__ Wv,
                                                const float* __restrict__ Wl) {
    __shared__ __align__(16) float As[8][132];
    __shared__ __align__(16) float Bs[8][132];
    __shared__ int stok[128];
    const int tid = threadIdx.x;
    const int rt  = blockIdx.y;                 // 0..63, <32 => vision
    const float* __restrict__ W = (rt < (TOK/128)) ? Wv : Wl;

    int myv = 0;
    if (tid < 128) {
        int t = g_idx[rt*128 + tid];
        stok[tid] = t;
        myv = (t >= 0);
    }
    if (!__syncthreads_or(myv)) return;

    const int obase = blockIdx.x * 128;
    const int lr = tid >> 1;                    // 0..127
    const int lc = (tid & 1) * 4;               // 0 or 4
    const int mytok = stok[lr];
    const float* __restrict__ xrow = X + (size_t)(mytok < 0 ? 0 : mytok) * HID;
    const float* __restrict__ wrow = W + (size_t)(obase + lr) * HID;
    const int ty = tid >> 4, tx = tid & 15;

    float acc[8][8];
    #pragma unroll
    for (int i = 0; i < 8; i++)
        #pragma unroll
        for (int j = 0; j < 8; j++) acc[i][j] = 0.f;

    float4 av = make_float4(0,0,0,0);
    if (mytok >= 0) av = *(const float4*)(xrow + lc);
    float4 bv = *(const float4*)(wrow + lc);

    for (int k0 = 0; k0 < HID; k0 += 8) {
        As[lc+0][lr]=av.x; As[lc+1][lr]=av.y; As[lc+2][lr]=av.z; As[lc+3][lr]=av.w;
        Bs[lc+0][lr]=bv.x; Bs[lc+1][lr]=bv.y; Bs[lc+2][lr]=bv.z; Bs[lc+3][lr]=bv.w;
        __syncthreads();
        int kn = k0 + 8;
        if (kn < HID) {
            av = make_float4(0,0,0,0);
            if (mytok >= 0) av = *(const float4*)(xrow + kn + lc);
            bv = *(const float4*)(wrow + kn + lc);
        }
        #pragma unroll
        for (int kk = 0; kk < 8; kk++) {
            float4 a0 = *(const float4*)&As[kk][ty*8];
            float4 a1 = *(const float4*)&As[kk][ty*8+4];
            float4 b0 = *(const float4*)&Bs[kk][tx*8];
            float4 b1 = *(const float4*)&Bs[kk][tx*8+4];
            float ra[8] = {a0.x,a0.y,a0.z,a0.w,a1.x,a1.y,a1.z,a1.w};
            float rb[8] = {b0.x,b0.y,b0.z,b0.w,b1.x,b1.y,b1.z,b1.w};
            #pragma unroll
            for (int i = 0; i < 8; i++)
                #pragma unroll
                for (int j = 0; j < 8; j++) acc[i][j] = fmaf(ra[i], rb[j], acc[i][j]);
        }
        __syncthreads();
    }

    // epilogue: scatter into q/k/v [B,NH,L,HD] (each 128-wide N tile = one head of one part)
    const int part = blockIdx.x >> 5;           // 0=q,1=k,2=v
    const int head = blockIdx.x & 31;
    float* dst = (part == 0) ? g_q : (part == 1) ? g_k : g_v;
    #pragma unroll
    for (int i = 0; i < 8; i++) {
        int m = ty*8 + i;
        int t = stok[m];
        if (t < 0) continue;
        int b = t >> 11, l = t & (SEQ-1);
        float* drow = dst + (((size_t)(b*NH + head))*SEQ + l)*HD + tx*8;
        *(float4*)(drow)   = make_float4(acc[i][0],acc[i][1],acc[i][2],acc[i][3]);
        *(float4*)(drow+4) = make_float4(acc[i][4],acc[i][5],acc[i][6],acc[i][7]);
    }
}

// ---------------- kernel 3: RoPE (in place on g_q, g_k) ----------------
__global__ void rope_kernel(const int* __restrict__ pos_ids) {
    int i = blockIdx.x * blockDim.x + threadIdx.x;     // [0, B*NH*SEQ*64)
    if (i >= BSZ*NH*SEQ*(HD/2)) return;
    int d = i & 63;
    int l = (i >> 6) & (SEQ-1);
    int h = (i >> 17) & (NH-1);
    int b = i >> 22;
    int pos = pos_ids[(b << 11) | l];
    float invf = powf(10000.f, -(float)d * (1.f/64.f));
    float ang = (float)pos * invf;
    float s, c;
    sincosf(ang, &s, &c);
    size_t base = (((size_t)(b*NH + h))*SEQ + l)*HD + d;
    float x1 = g_q[base], x2 = g_q[base+64];
    g_q[base]    = x1*c - x2*s;
    g_q[base+64] = x2*c + x1*s;
    x1 = g_k[base]; x2 = g_k[base+64];
    g_k[base]    = x1*c - x2*s;
    g_k[base+64] = x2*c + x1*s;
}

// ---------------- kernel 4: flash attention (fp32) ----------------
// grid (SEQ/64, B*NH); 256 threads; dynamic smem
__global__ __launch_bounds__(256) void attn_kernel() {
    extern __shared__ __align__(16) float sm[];
    float* Qs   = sm;                    // [64][129]
    float* Ks   = Qs + 64*129;           // [64][129]
    float* Vs   = Ks + 64*129;           // [64][132] (float4 rows)
    float* St   = Vs + 64*132;           // [64][65], stored [c][r] (transposed)
    float* mrow = St + 64*65;            // [64]
    float* lrow = mrow + 64;             // [64]
    float* srow = lrow + 64;             // [64]
    float* red  = srow + 64;             // [4][64]

    const int tid = threadIdx.x;
    const int bh  = blockIdx.y;
    const int q0  = blockIdx.x * 64;
    const size_t base = (size_t)bh * SEQ * HD;
    const float* __restrict__ Qg = g_q + base;
    const float* __restrict__ Kg = g_k + base;
    const float* __restrict__ Vg = g_v + base;
    const int w = tid >> 5, lane = tid & 31;
    const float qscale = 0.08838834764831845f;   // 1/sqrt(128)

    for (int r = w; r < 64; r += 8) {
        float4 qv = *(const float4*)(Qg + (size_t)(q0+r)*HD + lane*4);
        Qs[r*129 + lane*4+0] = qv.x*qscale;
        Qs[r*129 + lane*4+1] = qv.y*qscale;
        Qs[r*129 + lane*4+2] = qv.z*qscale;
        Qs[r*129 + lane*4+3] = qv.w*qscale;
    }
    if (tid < 64) { mrow[tid] = -CUDART_INF_F; lrow[tid] = 0.f; }

    const int ty = tid >> 4, tx = tid & 15;
    const int sr = tid & 63, seg = tid >> 6;
    float acc_o[4][8];
    #pragma unroll
    for (int i = 0; i < 4; i++)
        #pragma unroll
        for (int j = 0; j < 8; j++) acc_o[i][j] = 0.f;
    __syncthreads();

    for (int kt = 0; kt < SEQ/64; kt++) {
        const int k0 = kt * 64;
        for (int r = w; r < 64; r += 8) {
            float4 kv = *(const float4*)(Kg + (size_t)(k0+r)*HD + lane*4);
            Ks[r*129 + lane*4+0] = kv.x;
            Ks[r*129 + lane*4+1] = kv.y;
            Ks[r*129 + lane*4+2] = kv.z;
            Ks[r*129 + lane*4+3] = kv.w;
            float4 vv = *(const float4*)(Vg + (size_t)(k0+r)*HD + lane*4);
            *(float4*)&Vs[r*132 + lane*4] = vv;
        }
        __syncthreads();

        // S = Qscaled @ K^T, 4x4 micro-tile, write transposed into St[c][r]
        float accs[4][4];
        #pragma unroll
        for (int i = 0; i < 4; i++)
            #pragma unroll
            for (int j = 0; j < 4; j++) accs[i][j] = 0.f;
        #pragma unroll 4
        for (int d = 0; d < HD; d++) {
            float rq[4], rk[4];
            #pragma unroll
            for (int i = 0; i < 4; i++) rq[i] = Qs[(ty*4+i)*129 + d];
            #pragma unroll
            for (int j = 0; j < 4; j++) rk[j] = Ks[(tx*4+j)*129 + d];
            #pragma unroll
            for (int i = 0; i < 4; i++)
                #pragma unroll
                for (int j = 0; j < 4; j++) accs[i][j] = fmaf(rq[i], rk[j], accs[i][j]);
        }
        #pragma unroll
        for (int j = 0; j < 4; j++)
            #pragma unroll
            for (int i = 0; i < 4; i++)
                St[(tx*4+j)*65 + ty*4+i] = accs[i][j];
        __syncthreads();

        // row max (per row r=sr, 4 segments of 16 keys)
        float pm = -CUDART_INF_F;
        #pragma unroll
        for (int c = seg*16; c < seg*16+16; c++) pm = fmaxf(pm, St[c*65 + sr]);
        red[seg*64 + sr] = pm;
        __syncthreads();
        if (tid < 64) {
            float mo = mrow[tid];
            float mn = fmaxf(fmaxf(red[tid], red[64+tid]), fmaxf(red[128+tid], red[192+tid]));
            mn = fmaxf(mo, mn);
            mrow[tid] = mn;
            srow[tid] = expf(mo - mn);     // 0 on first tile (mo = -inf)
        }
        __syncthreads();

        // exp pass + partial sums, and rescale O accumulators
        float mr = mrow[sr];
        float ps = 0.f;
        #pragma unroll
        for (int c = seg*16; c < seg*16+16; c++) {
            float p = expf(St[c*65 + sr] - mr);
            St[c*65 + sr] = p;
            ps += p;
        }
        red[seg*64 + sr] = ps;
        #pragma unroll
        for (int i = 0; i < 4; i++) {
            float sc = srow[ty*4+i];
            #pragma unroll
            for (int j = 0; j < 8; j++) acc_o[i][j] *= sc;
        }
        __syncthreads();
        if (tid < 64)
            lrow[tid] = lrow[tid]*srow[tid] + red[tid]+red[64+tid]+red[128+tid]+red[192+tid];

        // O += P @ V  (P from St[c][r], V natural)
        #pragma unroll 2
        for (int c = 0; c < 64; c++) {
            float rp[4];
            #pragma unroll
            for (int i = 0; i < 4; i++) rp[i] = St[c*65 + ty*4+i];
            float4 v0 = *(const float4*)&Vs[c*132 + tx*8];
            float4 v1 = *(const float4*)&Vs[c*132 + tx*8 + 4];
            float rv[8] = {v0.x,v0.y,v0.z,v0.w,v1.x,v1.y,v1.z,v1.w};
            #pragma unroll
            for (int i = 0; i < 4; i++)
                #pragma unroll
                for (int j = 0; j < 8; j++) acc_o[i][j] = fmaf(rp[i], rv[j], acc_o[i][j]);
        }
        __syncthreads();
    }

    // finalize: divide by l, write ctx [B, L, H] (head-major)
    const int b = bh >> 5, h = bh & 31;
    #pragma unroll
    for (int i = 0; i < 4; i++) {
        int r = ty*4 + i;
        float inv = 1.f / lrow[r];
        float* drow = g_ctx + ((size_t)(b*SEQ) + q0 + r)*HID + h*HD + tx*8;
        *(float4*)(drow)   = make_float4(acc_o[i][0]*inv, acc_o[i][1]*inv, acc_o[i][2]*inv, acc_o[i][3]*inv);
        *(float4*)(drow+4) = make_float4(acc_o[i][4]*inv, acc_o[i][5]*inv, acc_o[i][6]*inv, acc_o[i][7]*inv);
    }
}

// ---------------- kernel 5: routed output dense ----------------
__global__ __launch_bounds__(256) void dense_gemm(const float* __restrict__ Wv,
                                                  const float* __restrict__ Wl,
                                                  float* __restrict__ out) {
    __shared__ __align__(16) float As[8][132];
    __shared__ __align__(16) float Bs[8][132];
    __shared__ int stok[128];
    const int tid = threadIdx.x;
    const int rt  = blockIdx.y;
    const float* __restrict__ W = (rt < (TOK/128)) ? Wv : Wl;

    int myv = 0;
    if (tid < 128) {
        int t = g_idx[rt*128 + tid];
        stok[tid] = t;
        myv = (t >= 0);
    }
    if (!__syncthreads_or(myv)) return;

    const int obase = blockIdx.x * 128;
    const int lr = tid >> 1;
    const int lc = (tid & 1) * 4;
    const int mytok = stok[lr];
    const float* __restrict__ xrow = g_ctx + (size_t)(mytok < 0 ? 0 : mytok) * HID;
    const float* __restrict__ wrow = W + (size_t)(obase + lr) * HID;
    const int ty = tid >> 4, tx = tid & 15;

    float acc[8][8];
    #pragma unroll
    for (int i = 0; i < 8; i++)
        #pragma unroll
        for (int j = 0; j < 8; j++) acc[i][j] = 0.f;

    float4 av = make_float4(0,0,0,0);
    if (mytok >= 0) av = *(const float4*)(xrow + lc);
    float4 bv = *(const float4*)(wrow + lc);

    for (int k0 = 0; k0 < HID; k0 += 8) {
        As[lc+0][lr]=av.x; As[lc+1][lr]=av.y; As[lc+2][lr]=av.z; As[lc+3][lr]=av.w;
        Bs[lc+0][lr]=bv.x; Bs[lc+1][lr]=bv.y; Bs[lc+2][lr]=bv.z; Bs[lc+3][lr]=bv.w;
        __syncthreads();
        int kn = k0 + 8;
        if (kn < HID) {
            av = make_float4(0,0,0,0);
            if (mytok >= 0) av = *(const float4*)(xrow + kn + lc);
            bv = *(const float4*)(wrow + kn + lc);
        }
        #pragma unroll
        for (int kk = 0; kk < 8; kk++) {
            float4 a0 = *(const float4*)&As[kk][ty*8];
            float4 a1 = *(const float4*)&As[kk][ty*8+4];
            float4 b0 = *(const float4*)&Bs[kk][tx*8];
            float4 b1 = *(const float4*)&Bs[kk][tx*8+4];
            float ra[8] = {a0.x,a0.y,a0.z,a0.w,a1.x,a1.y,a1.z,a1.w};
            float rb[8] = {b0.x,b0.y,b0.z,b0.w,b1.x,b1.y,b1.z,b1.w};
            #pragma unroll
            for (int i = 0; i < 8; i++)
                #pragma unroll
                for (int j = 0; j < 8; j++) acc[i][j] = fmaf(ra[i], rb[j], acc[i][j]);
        }
        __syncthreads();
    }

    #pragma unroll
    for (int i = 0; i < 8; i++) {
        int m = ty*8 + i;
        int t = stok[m];
        if (t < 0) continue;
        float* drow = out + (size_t)t*HID + obase + tx*8;
        *(float4*)(drow)   = make_float4(acc[i][0],acc[i][1],acc[i][2],acc[i][3]);
        *(float4*)(drow+4) = make_float4(acc[i][4],acc[i][5],acc[i][6],acc[i][7]);
    }
}

// ---------------- launch ----------------
extern "C" void kernel_launch(void* const* d_in, const int* in_sizes, int n_in,
                              void* d_out, int out_size) {
    const float* x   = (const float*)d_in[0];
    const int*   tt  = (const int*)d_in[1];
    const int*   pos = (const int*)d_in[2];
    /* d_in[3] attention_mask: all zeros, unused (matches reference math) */
    const float* wvq = (const float*)d_in[4];
    const float* wlq = (const float*)d_in[5];
    const float* wvd = (const float*)d_in[6];
    const float* wld = (const float*)d_in[7];
    float* out = (float*)d_out;

    route_kernel<<<1, 1024>>>(tt);
    qkv_gemm<<<dim3(QKV_N/128, 2*TOK/128), 256>>>(x, wvq, wlq);
    rope_kernel<<<(BSZ*NH*SEQ*(HD/2) + 255)/256, 256>>>(pos);

    const size_t attn_smem = (size_t)(64*129 + 64*129 + 64*132 + 64*65 + 3*64 + 4*64) * sizeof(float);
    cudaFuncSetAttribute(attn_kernel, cudaFuncAttributeMaxDynamicSharedMemorySize, (int)attn_smem);
    attn_kernel<<<dim3(SEQ/64, BSZ*NH), 256, attn_smem>>>();

    dense_gemm<<<dim3(HID/128, 2*TOK/128), 256>>>(wvd, wld, out);
}

// round 4
// speedup vs baseline: 2.5736x; 2.5736x over previous
#include <cuda_runtime.h>
#include <math_constants.h>
#include <math.h>
#include <stdint.h>

#define HID   4096
#define NH    32
#define HD    128
#define BSZ   2
#define SEQ   2048
#define TOK   (BSZ*SEQ)      /* 4096 */
#define QKV_N (3*HID)        /* 12288 */

// ---------------- device scratch (static, allocation-free) ----------------
__device__ int   g_idx[2*TOK];                       // [0,4096): vision slots, [4096,8192): language slots, -1 = empty
__device__ float g_q[(size_t)BSZ*NH*SEQ*HD];         // [B,NH,L,HD]
__device__ float g_k[(size_t)BSZ*NH*SEQ*HD];
__device__ float g_v[(size_t)BSZ*NH*SEQ*HD];
__device__ float g_ctx[(size_t)TOK*HID];             // [B,L,H] head-major within H

// ---------------- tf32 helpers ----------------
__device__ __forceinline__ uint32_t f2tf(float x) {
    uint32_t u; asm("cvt.rna.tf32.f32 %0, %1;" : "=r"(u) : "f"(x)); return u;
}
__device__ __forceinline__ void mma8(float c[4], const uint32_t a[4], const uint32_t b[2]) {
    asm volatile(
        "mma.sync.aligned.m16n8k8.row.col.f32.tf32.tf32.f32 "
        "{%0,%1,%2,%3},{%4,%5,%6,%7},{%8,%9},{%0,%1,%2,%3};"
        : "+f"(c[0]), "+f"(c[1]), "+f"(c[2]), "+f"(c[3])
        : "r"(a[0]), "r"(a[1]), "r"(a[2]), "r"(a[3]), "r"(b[0]), "r"(b[1]));
}

// ---------------- kernel 1: routing ----------------
__global__ void route_kernel(const int* __restrict__ tt) {
    __shared__ int cnt[2];
    int tid = threadIdx.x;
    if (tid < 2) cnt[tid] = 0;
    for (int i = tid; i < 2*TOK; i += blockDim.x) g_idx[i] = -1;
    __syncthreads();
    for (int t = tid; t < TOK; t += blockDim.x) {
        int l = t & (SEQ-1);
        int vm = (l < SEQ-1) && (tt[t] == 1) && (tt[t+1] == 1);
        int p = atomicAdd(&cnt[vm ? 0 : 1], 1);
        g_idx[(vm ? 0 : TOK) + p] = t;
    }
}

// ---------------- kernel 2/5: routed GEMM (tf32 tensor cores) ----------------
// C[slot, o] = sum_h X[tok(slot), h] * W[o, h]
// mode 0: X = input hidden states, epilogue scatters into g_q/g_k/g_v (grid.x = 96)
// mode 1: X = g_ctx (device symbol),  epilogue writes routed dense out (grid.x = 32)
// 256 threads = 8 warps (2 m-warps x 4 n-warps); warp tile 64x32; K-step 32.
__global__ __launch_bounds__(256) void routed_gemm(const float* __restrict__ Xin,
                                                   const float* __restrict__ Wv,
                                                   const float* __restrict__ Wl,
                                                   float* __restrict__ out,
                                                   int mode) {
    __shared__ uint32_t As[128][36];      // [m][k] tf32 bits, pad 36
    __shared__ uint32_t Bs[128][36];      // [n][k]
    __shared__ int stok[128];
    const int tid = threadIdx.x;
    const int rt  = blockIdx.y;           // 0..63, <32 => vision
    const float* __restrict__ W = (rt < (TOK/128)) ? Wv : Wl;
    const float* __restrict__ X = (mode == 0) ? Xin : (const float*)g_ctx;

    int myv = 0;
    if (tid < 128) {
        int t = g_idx[rt*128 + tid];
        stok[tid] = t;
        myv = (t >= 0);
    }
    if (!__syncthreads_or(myv)) return;

    const int obase = blockIdx.x * 128;
    const int lr = tid >> 1;              // 0..127 (row)
    const int lk = (tid & 1) * 16;        // 0 or 16 (k offset)
    const int tokr = stok[lr];
    const float* __restrict__ xrow = X + (size_t)(tokr < 0 ? 0 : tokr) * HID;
    const float* __restrict__ wrow = W + (size_t)(obase + lr) * HID;

    const int w = tid >> 5, lane = tid & 31;
    const int mw = w >> 2, nw = w & 3;
    const int g = lane >> 2, t = lane & 3;

    float c[4][4][4];
    #pragma unroll
    for (int mi = 0; mi < 4; mi++)
        #pragma unroll
        for (int ni = 0; ni < 4; ni++)
            #pragma unroll
            for (int e = 0; e < 4; e++) c[mi][ni][e] = 0.f;

    float4 pa[4], pb[4];
    #pragma unroll
    for (int j = 0; j < 4; j++) {
        pa[j] = (tokr >= 0) ? *(const float4*)(xrow + lk + j*4) : make_float4(0,0,0,0);
        pb[j] = *(const float4*)(wrow + lk + j*4);
    }

    for (int k0 = 0; k0 < HID; k0 += 32) {
        #pragma unroll
        for (int j = 0; j < 4; j++) {
            uint4 ua = make_uint4(f2tf(pa[j].x), f2tf(pa[j].y), f2tf(pa[j].z), f2tf(pa[j].w));
            uint4 ub = make_uint4(f2tf(pb[j].x), f2tf(pb[j].y), f2tf(pb[j].z), f2tf(pb[j].w));
            *(uint4*)&As[lr][lk + j*4] = ua;
            *(uint4*)&Bs[lr][lk + j*4] = ub;
        }
        __syncthreads();
        int kn = k0 + 32;
        if (kn < HID) {
            #pragma unroll
            for (int j = 0; j < 4; j++) {
                pa[j] = (tokr >= 0) ? *(const float4*)(xrow + kn + lk + j*4) : make_float4(0,0,0,0);
                pb[j] = *(const float4*)(wrow + kn + lk + j*4);
            }
        }
        #pragma unroll
        for (int kk = 0; kk < 32; kk += 8) {
            uint32_t af[4][4], bf[4][2];
            #pragma unroll
            for (int mi = 0; mi < 4; mi++) {
                int m0 = mw*64 + mi*16;
                af[mi][0] = As[m0+g][kk+t];
                af[mi][1] = As[m0+g+8][kk+t];
                af[mi][2] = As[m0+g][kk+t+4];
                af[mi][3] = As[m0+g+8][kk+t+4];
            }
            #pragma unroll
            for (int ni = 0; ni < 4; ni++) {
                int n0 = nw*32 + ni*8;
                bf[ni][0] = Bs[n0+g][kk+t];
                bf[ni][1] = Bs[n0+g][kk+t+4];
            }
            #pragma unroll
            for (int mi = 0; mi < 4; mi++)
                #pragma unroll
                for (int ni = 0; ni < 4; ni++)
                    mma8(c[mi][ni], af[mi], bf[ni]);
        }
        __syncthreads();
    }

    if (mode == 0) {
        const int part = blockIdx.x >> 5;       // 0=q,1=k,2=v
        const int head = blockIdx.x & 31;
        float* dst = (part == 0) ? g_q : (part == 1) ? g_k : g_v;
        #pragma unroll
        for (int mi = 0; mi < 4; mi++)
            #pragma unroll
            for (int e2 = 0; e2 < 2; e2++) {
                int m = mw*64 + mi*16 + g + e2*8;
                int tk = stok[m];
                if (tk < 0) continue;
                int b = tk >> 11, l = tk & (SEQ-1);
                float* drow = dst + (((size_t)(b*NH + head))*SEQ + l)*HD;
                #pragma unroll
                for (int ni = 0; ni < 4; ni++) {
                    int d0 = nw*32 + ni*8 + 2*t;
                    *(float2*)(drow + d0) = make_float2(c[mi][ni][e2*2], c[mi][ni][e2*2+1]);
                }
            }
    } else {
        #pragma unroll
        for (int mi = 0; mi < 4; mi++)
            #pragma unroll
            for (int e2 = 0; e2 < 2; e2++) {
                int m = mw*64 + mi*16 + g + e2*8;
                int tk = stok[m];
                if (tk < 0) continue;
                float* drow = out + (size_t)tk*HID + obase;
                #pragma unroll
                for (int ni = 0; ni < 4; ni++) {
                    int d0 = nw*32 + ni*8 + 2*t;
                    *(float2*)(drow + d0) = make_float2(c[mi][ni][e2*2], c[mi][ni][e2*2+1]);
                }
            }
    }
}

// ---------------- kernel 3: RoPE (in place on g_q, g_k) ----------------
__global__ void rope_kernel(const int* __restrict__ pos_ids) {
    int i = blockIdx.x * blockDim.x + threadIdx.x;     // [0, B*NH*SEQ*64)
    if (i >= BSZ*NH*SEQ*(HD/2)) return;
    int d = i & 63;
    int l = (i >> 6) & (SEQ-1);
    int h = (i >> 17) & (NH-1);
    int b = i >> 22;
    int pos = pos_ids[(b << 11) | l];
    float invf = powf(10000.f, -(float)d * (1.f/64.f));
    float ang = (float)pos * invf;
    float s, cn;
    sincosf(ang, &s, &cn);
    size_t base = (((size_t)(b*NH + h))*SEQ + l)*HD + d;
    float x1 = g_q[base], x2 = g_q[base+64];
    g_q[base]    = x1*cn - x2*s;
    g_q[base+64] = x2*cn + x1*s;
    x1 = g_k[base]; x2 = g_k[base+64];
    g_k[base]    = x1*cn - x2*s;
    g_k[base+64] = x2*cn + x1*s;
}

// ---------------- kernel 4: flash attention (tf32 tensor cores) ----------------
// grid (SEQ/64, B*NH); 256 threads = 8 warps.
// S: M=64(q) N=64(k) K=128(d), warps 2x4 -> warp tile 32x16.
// PV: M=64(q) N=128(d) K=64(k), warps 2x4 -> warp tile 32x32.
__global__ __launch_bounds__(256) void attn_kernel() {
    extern __shared__ __align__(16) uint32_t smu[];
    uint32_t* Qs = smu;                   // [64][132] tf32
    uint32_t* Ks = Qs + 64*132;           // [64][132] tf32
    uint32_t* Vs = Ks + 64*132;           // [64][132] tf32
    float*    St = (float*)(Vs + 64*132); // [64][68], stored [c][r]
    float*  mrow = St + 64*68;            // [64]
    float*  lrow = mrow + 64;             // [64]
    float*  srow = lrow + 64;             // [64]
    float*  red  = srow + 64;             // [4][64]

    const int tid = threadIdx.x;
    const int bh  = blockIdx.y;
    const int q0  = blockIdx.x * 64;
    const size_t base = (size_t)bh * SEQ * HD;
    const float* __restrict__ Qg = g_q + base;
    const float* __restrict__ Kg = g_k + base;
    const float* __restrict__ Vg = g_v + base;
    const int w = tid >> 5, lane = tid & 31;
    const int g = lane >> 2, t = lane & 3;
    const int mw = w >> 2, nw = w & 3;
    const float qscale = 0.08838834764831845f;   // 1/sqrt(128)

    for (int r = w; r < 64; r += 8) {
        float4 qv = *(const float4*)(Qg + (size_t)(q0+r)*HD + lane*4);
        uint32_t* qd = Qs + r*132 + lane*4;
        qd[0] = f2tf(qv.x*qscale); qd[1] = f2tf(qv.y*qscale);
        qd[2] = f2tf(qv.z*qscale); qd[3] = f2tf(qv.w*qscale);
    }
    if (tid < 64) { mrow[tid] = -CUDART_INF_F; lrow[tid] = 0.f; }

    const int sr = tid & 63, seg = tid >> 6;
    float co[2][4][4];
    #pragma unroll
    for (int mi = 0; mi < 2; mi++)
        #pragma unroll
        for (int ni = 0; ni < 4; ni++)
            #pragma unroll
            for (int e = 0; e < 4; e++) co[mi][ni][e] = 0.f;
    __syncthreads();

    for (int kt = 0; kt < SEQ/64; kt++) {
        const int k0 = kt * 64;
        for (int r = w; r < 64; r += 8) {
            float4 kv = *(const float4*)(Kg + (size_t)(k0+r)*HD + lane*4);
            uint32_t* kd = Ks + r*132 + lane*4;
            kd[0] = f2tf(kv.x); kd[1] = f2tf(kv.y); kd[2] = f2tf(kv.z); kd[3] = f2tf(kv.w);
            float4 vv = *(const float4*)(Vg + (size_t)(k0+r)*HD + lane*4);
            uint32_t* vd = Vs + r*132 + lane*4;
            vd[0] = f2tf(vv.x); vd[1] = f2tf(vv.y); vd[2] = f2tf(vv.z); vd[3] = f2tf(vv.w);
        }
        __syncthreads();

        // ---- S = Qscaled @ K^T ----
        float cs[2][2][4];
        #pragma unroll
        for (int mi = 0; mi < 2; mi++)
            #pragma unroll
            for (int ni = 0; ni < 2; ni++)
                #pragma unroll
                for (int e = 0; e < 4; e++) cs[mi][ni][e] = 0.f;
        #pragma unroll
        for (int kk = 0; kk < HD; kk += 8) {
            uint32_t af[2][4], bf[2][2];
            #pragma unroll
            for (int mi = 0; mi < 2; mi++) {
                int m0 = mw*32 + mi*16;
                const uint32_t* qp = Qs + (m0+g)*132 + kk + t;
                af[mi][0] = qp[0];
                af[mi][2] = qp[4];
                af[mi][1] = qp[8*132];
                af[mi][3] = qp[8*132 + 4];
            }
            #pragma unroll
            for (int ni = 0; ni < 2; ni++) {
                int n0 = nw*16 + ni*8;
                const uint32_t* kp = Ks + (n0+g)*132 + kk + t;
                bf[ni][0] = kp[0];
                bf[ni][1] = kp[4];
            }
            #pragma unroll
            for (int mi = 0; mi < 2; mi++)
                #pragma unroll
                for (int ni = 0; ni < 2; ni++)
                    mma8(cs[mi][ni], af[mi], bf[ni]);
        }
        // store S transposed: St[c][r]
        #pragma unroll
        for (int mi = 0; mi < 2; mi++)
            #pragma unroll
            for (int ni = 0; ni < 2; ni++)
                #pragma unroll
                for (int e = 0; e < 4; e++) {
                    int rr = mw*32 + mi*16 + g + (e >> 1)*8;
                    int cc = nw*16 + ni*8 + 2*t + (e & 1);
                    St[cc*68 + rr] = cs[mi][ni][e];
                }
        __syncthreads();

        // ---- row max ----
        float pm = -CUDART_INF_F;
        #pragma unroll
        for (int c = seg*16; c < seg*16+16; c++) pm = fmaxf(pm, St[c*68 + sr]);
        red[seg*64 + sr] = pm;
        __syncthreads();
        if (tid < 64) {
            float mo = mrow[tid];
            float mn = fmaxf(fmaxf(red[tid], red[64+tid]), fmaxf(red[128+tid], red[192+tid]));
            mn = fmaxf(mo, mn);
            mrow[tid] = mn;
            srow[tid] = __expf(mo - mn);     // 0 on first tile
        }
        __syncthreads();

        // ---- exp pass + partial sums + rescale O ----
        float mr = mrow[sr];
        float ps = 0.f;
        #pragma unroll
        for (int c = seg*16; c < seg*16+16; c++) {
            float p = __expf(St[c*68 + sr] - mr);
            St[c*68 + sr] = p;
            ps += p;
        }
        red[seg*64 + sr] = ps;
        #pragma unroll
        for (int mi = 0; mi < 2; mi++) {
            int r1 = mw*32 + mi*16 + g;
            float s0 = srow[r1], s1 = srow[r1+8];
            #pragma unroll
            for (int ni = 0; ni < 4; ni++) {
                co[mi][ni][0] *= s0; co[mi][ni][1] *= s0;
                co[mi][ni][2] *= s1; co[mi][ni][3] *= s1;
            }
        }
        __syncthreads();
        if (tid < 64)
            lrow[tid] = lrow[tid]*srow[tid] + red[tid]+red[64+tid]+red[128+tid]+red[192+tid];

        // ---- O += P @ V ----
        #pragma unroll
        for (int kk = 0; kk < 64; kk += 8) {
            uint32_t af[2][4], bf[4][2];
            #pragma unroll
            for (int mi = 0; mi < 2; mi++) {
                int m0 = mw*32 + mi*16;
                af[mi][0] = f2tf(St[(kk+t)*68   + m0+g]);
                af[mi][1] = f2tf(St[(kk+t)*68   + m0+g+8]);
                af[mi][2] = f2tf(St[(kk+t+4)*68 + m0+g]);
                af[mi][3] = f2tf(St[(kk+t+4)*68 + m0+g+8]);
            }
            #pragma unroll
            for (int ni = 0; ni < 4; ni++) {
                int n0 = nw*32 + ni*8;
                bf[ni][0] = Vs[(kk+t)*132   + n0+g];
                bf[ni][1] = Vs[(kk+t+4)*132 + n0+g];
            }
            #pragma unroll
            for (int mi = 0; mi < 2; mi++)
                #pragma unroll
                for (int ni = 0; ni < 4; ni++)
                    mma8(co[mi][ni], af[mi], bf[ni]);
        }
        __syncthreads();
    }

    // finalize: divide by l, write ctx [B, L, H]
    const int b = bh >> 5, h = bh & 31;
    #pragma unroll
    for (int mi = 0; mi < 2; mi++)
        #pragma unroll
        for (int e2 = 0; e2 < 2; e2++) {
            int r = mw*32 + mi*16 + g + e2*8;
            float inv = 1.f / lrow[r];
            float* drow = g_ctx + ((size_t)(b*SEQ) + q0 + r)*HID + h*HD;
            #pragma unroll
            for (int ni = 0; ni < 4; ni++) {
                int d0 = nw*32 + ni*8 + 2*t;
                *(float2*)(drow + d0) = make_float2(co[mi][ni][e2*2]*inv, co[mi][ni][e2*2+1]*inv);
            }
        }
}

// ---------------- launch ----------------
extern "C" void kernel_launch(void* const* d_in, const int* in_sizes, int n_in,
                              void* d_out, int out_size) {
    const float* x   = (const float*)d_in[0];
    const int*   tt  = (const int*)d_in[1];
    const int*   pos = (const int*)d_in[2];
    /* d_in[3] attention_mask: all zeros, unused (matches reference math) */
    const float* wvq = (const float*)d_in[4];
    const float* wlq = (const float*)d_in[5];
    const float* wvd = (const float*)d_in[6];
    const float* wld = (const float*)d_in[7];
    float* out = (float*)d_out;

    route_kernel<<<1, 1024>>>(tt);
    routed_gemm<<<dim3(QKV_N/128, 2*TOK/128), 256>>>(x, wvq, wlq, nullptr, 0);
    rope_kernel<<<(BSZ*NH*SEQ*(HD/2) + 255)/256, 256>>>(pos);

    const size_t attn_smem = (size_t)(3*64*132 + 64*68 + 3*64 + 4*64) * 4;
    cudaFuncSetAttribute(attn_kernel, cudaFuncAttributeMaxDynamicSharedMemorySize, (int)attn_smem);
    attn_kernel<<<dim3(SEQ/64, BSZ*NH), 256, attn_smem>>>();

    routed_gemm<<<dim3(HID/128, 2*TOK/128), 256>>>(nullptr, wvd, wld, out, 1);
}

// round 6
// speedup vs baseline: 5.1101x; 1.9856x over previous
#include <cuda_runtime.h>
#include <cuda_fp16.h>
#include <math_constants.h>
#include <math.h>
#include <stdint.h>

#define HID   4096
#define NH    32
#define HD    128
#define BSZ   2
#define SEQ   2048
#define TOK   (BSZ*SEQ)      /* 4096 */
#define QKV_N (3*HID)        /* 12288 */

// ---------------- device scratch (static, allocation-free) ----------------
__device__ int    g_idx[2*TOK];                       // routed slots, -1 = empty
__device__ float  g_q[(size_t)BSZ*NH*SEQ*HD];         // [B,NH,L,HD] fp32 (pre-RoPE)
__device__ float  g_k[(size_t)BSZ*NH*SEQ*HD];
__device__ float  g_v[(size_t)BSZ*NH*SEQ*HD];

// fp16 operand copies
#define OFF_VQ  ((size_t)0)
#define OFF_LQ  ((size_t)QKV_N*HID)
#define OFF_VD  ((size_t)2*QKV_N*HID)
#define OFF_LD  ((size_t)2*QKV_N*HID + (size_t)HID*HID)
#define W_TOT   ((size_t)2*QKV_N*HID + (size_t)2*HID*HID)
__device__ __half g_wh[W_TOT];                        // all 4 weight matrices, fp16
__device__ __half g_xh[(size_t)TOK*HID];              // input hidden, fp16
__device__ __half g_ch[(size_t)TOK*HID];              // attention context, fp16
__device__ __half g_qh[(size_t)BSZ*NH*SEQ*HD];        // RoPE'd + scaled Q, fp16
__device__ __half g_kh[(size_t)BSZ*NH*SEQ*HD];        // RoPE'd K, fp16
__device__ __half g_vth[(size_t)BSZ*NH*HD*SEQ];       // V transposed [B,NH,HD,SEQ], fp16

// ---------------- helpers ----------------
__device__ __forceinline__ uint32_t pack_h2(float x, float y) {
    __half2 h = __floats2half2_rn(x, y);
    return *reinterpret_cast<uint32_t*>(&h);
}
__device__ __forceinline__ void mma16(float c[4], const uint32_t a[4], const uint32_t b[2]) {
    asm volatile(
        "mma.sync.aligned.m16n8k16.row.col.f32.f16.f16.f32 "
        "{%0,%1,%2,%3},{%4,%5,%6,%7},{%8,%9},{%0,%1,%2,%3};"
        : "+f"(c[0]), "+f"(c[1]), "+f"(c[2]), "+f"(c[3])
        : "r"(a[0]), "r"(a[1]), "r"(a[2]), "r"(a[3]), "r"(b[0]), "r"(b[1]));
}

// ---------------- kernel 1: routing ----------------
__global__ void route_kernel(const int* __restrict__ tt) {
    __shared__ int cnt[2];
    int tid = threadIdx.x;
    if (tid < 2) cnt[tid] = 0;
    for (int i = tid; i < 2*TOK; i += blockDim.x) g_idx[i] = -1;
    __syncthreads();
    for (int t = tid; t < TOK; t += blockDim.x) {
        int l = t & (SEQ-1);
        int vm = (l < SEQ-1) && (tt[t] == 1) && (tt[t+1] == 1);
        int p = atomicAdd(&cnt[vm ? 0 : 1], 1);
        g_idx[(vm ? 0 : TOK) + p] = t;
    }
}

// ---------------- fp16 conversion kernels ----------------
__global__ void cvt_w_kernel(const float* __restrict__ src, size_t off, int n4) {
    int i = blockIdx.x * blockDim.x + threadIdx.x;
    if (i >= n4) return;
    float4 v = ((const float4*)src)[i];
    ((uint2*)(g_wh + off))[i] = make_uint2(pack_h2(v.x, v.y), pack_h2(v.z, v.w));
}
__global__ void cvt_x_kernel(const float* __restrict__ src, int n4) {
    int i = blockIdx.x * blockDim.x + threadIdx.x;
    if (i >= n4) return;
    float4 v = ((const float4*)src)[i];
    ((uint2*)g_xh)[i] = make_uint2(pack_h2(v.x, v.y), pack_h2(v.z, v.w));
}

// ---------------- kernel 2/5: routed GEMM (fp16 HMMA) ----------------
// C[slot, o] = sum_h X[tok(slot), h] * W[o, h]
// mode 0: X = g_xh, scatter epilogue -> g_q/g_k/g_v (grid.x = 96)
// mode 1: X = g_ch, epilogue -> out (grid.x = 32)
// 256 threads = 8 warps (2 m x 4 n), warp tile 64x32, K-chunk 32 halves.
__global__ __launch_bounds__(256) void hgemm(float* __restrict__ out, int mode) {
    __shared__ __align__(16) uint32_t As[128*20];   // [row][16 u32 data + 4 pad]
    __shared__ __align__(16) uint32_t Bs[128*20];
    __shared__ int stok[128];
    const int tid = threadIdx.x;
    const int rt  = blockIdx.y;                     // <32 => vision

    int myv = 0;
    if (tid < 128) {
        int t = g_idx[rt*128 + tid];
        stok[tid] = t;
        myv = (t >= 0);
    }
    if (!__syncthreads_or(myv)) return;

    const size_t woff = (mode == 0)
        ? (rt < (TOK/128) ? OFF_VQ : OFF_LQ)
        : (rt < (TOK/128) ? OFF_VD : OFF_LD);
    const int obase = blockIdx.x * 128;
    const int lr = tid >> 1, lc = (tid & 1) * 16;   // row 0..127, half-offset 0/16
    const int tokr = stok[lr];
    const __half* __restrict__ Xh = (mode == 0) ? g_xh : g_ch;
    const __half* __restrict__ xrow = Xh + (size_t)(tokr < 0 ? 0 : tokr) * HID;
    const __half* __restrict__ wrow = g_wh + woff + (size_t)(obase + lr) * HID;

    const int w = tid >> 5, lane = tid & 31;
    const int mw = w >> 2, nw = w & 3;
    const int g = lane >> 2, t = lane & 3;

    float c[4][4][4];
    #pragma unroll
    for (int mi = 0; mi < 4; mi++)
        #pragma unroll
        for (int ni = 0; ni < 4; ni++)
            #pragma unroll
            for (int e = 0; e < 4; e++) c[mi][ni][e] = 0.f;

    uint4 pa0 = *(const uint4*)(xrow + lc);
    uint4 pa1 = *(const uint4*)(xrow + lc + 8);
    uint4 pb0 = *(const uint4*)(wrow + lc);
    uint4 pb1 = *(const uint4*)(wrow + lc + 8);

    for (int k0 = 0; k0 < HID; k0 += 32) {
        const int sb = lr*20 + (tid & 1)*8;
        *(uint4*)&As[sb]   = pa0; *(uint4*)&As[sb+4] = pa1;
        *(uint4*)&Bs[sb]   = pb0; *(uint4*)&Bs[sb+4] = pb1;
        __syncthreads();
        const int kn = k0 + 32;
        if (kn < HID) {
            pa0 = *(const uint4*)(xrow + kn + lc);
            pa1 = *(const uint4*)(xrow + kn + lc + 8);
            pb0 = *(const uint4*)(wrow + kn + lc);
            pb1 = *(const uint4*)(wrow + kn + lc + 8);
        }
        #pragma unroll
        for (int kb = 0; kb < 2; kb++) {
            uint32_t af[4][4], bf[4][2];
            #pragma unroll
            for (int mi = 0; mi < 4; mi++) {
                const uint32_t* ap = &As[(mw*64 + mi*16 + g)*20 + kb*8 + t];
                af[mi][0] = ap[0]; af[mi][1] = ap[8*20];
                af[mi][2] = ap[4]; af[mi][3] = ap[8*20 + 4];
            }
            #pragma unroll
            for (int ni = 0; ni < 4; ni++) {
                const uint32_t* bp = &Bs[(nw*32 + ni*8 + g)*20 + kb*8 + t];
                bf[ni][0] = bp[0]; bf[ni][1] = bp[4];
            }
            #pragma unroll
            for (int mi = 0; mi < 4; mi++)
                #pragma unroll
                for (int ni = 0; ni < 4; ni++)
                    mma16(c[mi][ni], af[mi], bf[ni]);
        }
        __syncthreads();
    }

    if (mode == 0) {
        const int part = blockIdx.x >> 5;
        const int head = blockIdx.x & 31;
        float* dst = (part == 0) ? g_q : (part == 1) ? g_k : g_v;
        #pragma unroll
        for (int mi = 0; mi < 4; mi++)
            #pragma unroll
            for (int e2 = 0; e2 < 2; e2++) {
                int m = mw*64 + mi*16 + g + e2*8;
                int tk = stok[m];
                if (tk < 0) continue;
                int b = tk >> 11, l = tk & (SEQ-1);
                float* drow = dst + (((size_t)(b*NH + head))*SEQ + l)*HD;
                #pragma unroll
                for (int ni = 0; ni < 4; ni++) {
                    int d0 = nw*32 + ni*8 + 2*t;
                    *(float2*)(drow + d0) = make_float2(c[mi][ni][e2*2], c[mi][ni][e2*2+1]);
                }
            }
    } else {
        #pragma unroll
        for (int mi = 0; mi < 4; mi++)
            #pragma unroll
            for (int e2 = 0; e2 < 2; e2++) {
                int m = mw*64 + mi*16 + g + e2*8;
                int tk = stok[m];
                if (tk < 0) continue;
                float* drow = out + (size_t)tk*HID + obase;
                #pragma unroll
                for (int ni = 0; ni < 4; ni++) {
                    int d0 = nw*32 + ni*8 + 2*t;
                    *(float2*)(drow + d0) = make_float2(c[mi][ni][e2*2], c[mi][ni][e2*2+1]);
                }
            }
    }
}

// ---------------- kernel 3: RoPE -> fp16 Q (scaled), K ----------------
__global__ void rope_kernel(const int* __restrict__ pos_ids) {
    int i = blockIdx.x * blockDim.x + threadIdx.x;     // B*NH*SEQ*32
    if (i >= BSZ*NH*SEQ*32) return;
    int j = i & 31;                  // handles dims 2j, 2j+1 (+64 partners)
    int l = (i >> 5) & (SEQ-1);
    int h = (i >> 16) & (NH-1);
    int b = i >> 21;
    int pos = pos_ids[(b << 11) | l];
    float f0 = powf(10000.f, -(float)(2*j)   * (1.f/64.f));
    float f1 = powf(10000.f, -(float)(2*j+1) * (1.f/64.f));
    float s0, c0, s1, c1;
    sincosf((float)pos * f0, &s0, &c0);
    sincosf((float)pos * f1, &s1, &c1);
    const size_t base = (((size_t)(b*NH + h))*SEQ + l)*HD;
    const float qs = 0.08838834764831845f;   // 1/sqrt(128)

    float2 qa = *(const float2*)(g_q + base + 2*j);
    float2 qb = *(const float2*)(g_q + base + 2*j + 64);
    *(uint32_t*)(g_qh + base + 2*j)      = pack_h2((qa.x*c0 - qb.x*s0)*qs, (qa.y*c1 - qb.y*s1)*qs);
    *(uint32_t*)(g_qh + base + 2*j + 64) = pack_h2((qb.x*c0 + qa.x*s0)*qs, (qb.y*c1 + qa.y*s1)*qs);

    float2 ka = *(const float2*)(g_k + base + 2*j);
    float2 kb = *(const float2*)(g_k + base + 2*j + 64);
    *(uint32_t*)(g_kh + base + 2*j)      = pack_h2(ka.x*c0 - kb.x*s0, ka.y*c1 - kb.y*s1);
    *(uint32_t*)(g_kh + base + 2*j + 64) = pack_h2(kb.x*c0 + ka.x*s0, kb.y*c1 + ka.y*s1);
}

// ---------------- kernel 3b: V transpose -> fp16 [B,NH,HD,SEQ] ----------------
__global__ void vtrans_kernel() {
    __shared__ float ts[32][33];
    const int bh = blockIdx.z;
    const int l0 = blockIdx.y * 32, d0 = blockIdx.x * 32;
    const int tx = threadIdx.x, ty = threadIdx.y;       // (32,8)
    const float* __restrict__ src = g_v + ((size_t)bh*SEQ + l0)*HD + d0;
    #pragma unroll
    for (int k = 0; k < 4; k++)
        ts[ty + 8*k][tx] = src[(size_t)(ty + 8*k)*HD + tx];
    __syncthreads();
    __half* dst = g_vth + ((size_t)bh*HD + d0)*SEQ + l0;
    #pragma unroll
    for (int k = 0; k < 4; k++)
        dst[(size_t)(ty + 8*k)*SEQ + tx] = __float2half(ts[tx][ty + 8*k]);
}

// ---------------- kernel 4: flash attention (fp16 HMMA, 2 CTA/SM) ----------------
// grid (SEQ/64, B*NH); 256 threads = 8 warps (2 m x 4 n).
// S: 64x64 K=128;  PV: 64x128 K=64 with fp16 P buffer + transposed V tiles.
__global__ __launch_bounds__(256, 2) void attn_kernel() {
    extern __shared__ __align__(16) uint32_t smu[];
    uint32_t* Qs = smu;                    // [64][68] u32 (2 halves each)
    uint32_t* Ks = smu + 4352;             // [64][68]
    uint32_t* Vt = smu + 8704;             // [128][36]  (d rows, key pairs)
    uint32_t* Ph = smu + 13312;            // [32][72]   (key pairs, query cols)
    float*    St = (float*)(smu + 15616);  // [64][68] fp32, stored [key][query]
    float*  mrow = (float*)(smu + 19968);
    float*  lrow = mrow + 64;
    float*  srow = lrow + 64;
    float*  red  = srow + 64;              // [4][64]

    const int tid = threadIdx.x;
    const int bh  = blockIdx.y;
    const int q0  = blockIdx.x * 64;
    const __half* __restrict__ Qg = g_qh  + (size_t)bh * SEQ * HD;
    const __half* __restrict__ Kg = g_kh  + (size_t)bh * SEQ * HD;
    const __half* __restrict__ Vg = g_vth + (size_t)bh * HD * SEQ;
    const int w = tid >> 5, lane = tid & 31;
    const int g = lane >> 2, t = lane & 3;
    const int mw = w >> 2, nw = w & 3;

    for (int r = w; r < 64; r += 8) {
        uint2 qv = *(const uint2*)(Qg + (size_t)(q0+r)*HD + lane*4);
        Qs[r*68 + lane*2]     = qv.x;
        Qs[r*68 + lane*2 + 1] = qv.y;
    }
    if (tid < 64) { mrow[tid] = -CUDART_INF_F; lrow[tid] = 0.f; }

    const int sr = tid & 63, seg = tid >> 6;
    float co[2][4][4];
    #pragma unroll
    for (int mi = 0; mi < 2; mi++)
        #pragma unroll
        for (int ni = 0; ni < 4; ni++)
            #pragma unroll
            for (int e = 0; e < 4; e++) co[mi][ni][e] = 0.f;
    __syncthreads();

    for (int kt = 0; kt < SEQ/64; kt++) {
        const int k0 = kt * 64;
        for (int r = w; r < 64; r += 8) {
            uint2 kv = *(const uint2*)(Kg + (size_t)(k0+r)*HD + lane*4);
            Ks[r*68 + lane*2]     = kv.x;
            Ks[r*68 + lane*2 + 1] = kv.y;
        }
        #pragma unroll
        for (int it = 0; it < 4; it++) {
            int chunk = tid + it*256;          // 0..1023
            int row = chunk >> 3, c4 = chunk & 7;
            uint4 vv = *(const uint4*)(Vg + (size_t)row*SEQ + k0 + c4*8);
            *(uint4*)&Vt[row*36 + c4*4] = vv;
        }
        __syncthreads();

        // ---- S = Qscaled @ K^T (fp16, k16 steps) ----
        float cs[2][2][4];
        #pragma unroll
        for (int mi = 0; mi < 2; mi++)
            #pragma unroll
            for (int ni = 0; ni < 2; ni++)
                #pragma unroll
                for (int e = 0; e < 4; e++) cs[mi][ni][e] = 0.f;
        #pragma unroll
        for (int kb = 0; kb < 8; kb++) {
            uint32_t af[2][4], bf[2][2];
            #pragma unroll
            for (int mi = 0; mi < 2; mi++) {
                const uint32_t* ap = &Qs[(mw*32 + mi*16 + g)*68 + kb*8 + t];
                af[mi][0] = ap[0]; af[mi][1] = ap[8*68];
                af[mi][2] = ap[4]; af[mi][3] = ap[8*68 + 4];
            }
            #pragma unroll
            for (int ni = 0; ni < 2; ni++) {
                const uint32_t* bp = &Ks[(nw*16 + ni*8 + g)*68 + kb*8 + t];
                bf[ni][0] = bp[0]; bf[ni][1] = bp[4];
            }
            #pragma unroll
            for (int mi = 0; mi < 2; mi++)
                #pragma unroll
                for (int ni = 0; ni < 2; ni++)
                    mma16(cs[mi][ni], af[mi], bf[ni]);
        }
        // store S transposed: St[key][query]
        #pragma unroll
        for (int mi = 0; mi < 2; mi++)
            #pragma unroll
            for (int ni = 0; ni < 2; ni++)
                #pragma unroll
                for (int e = 0; e < 4; e++) {
                    int rr = mw*32 + mi*16 + g + (e >> 1)*8;
                    int cc = nw*16 + ni*8 + 2*t + (e & 1);
                    St[cc*68 + rr] = cs[mi][ni][e];
                }
        __syncthreads();

        // ---- row max ----
        float pm = -CUDART_INF_F;
        #pragma unroll
        for (int c = seg*16; c < seg*16+16; c++) pm = fmaxf(pm, St[c*68 + sr]);
        red[seg*64 + sr] = pm;
        __syncthreads();
        if (tid < 64) {
            float mo = mrow[tid];
            float mn = fmaxf(fmaxf(red[tid], red[64+tid]), fmaxf(red[128+tid], red[192+tid]));
            mn = fmaxf(mo, mn);
            mrow[tid] = mn;
            srow[tid] = __expf(mo - mn);
        }
        __syncthreads();

        // ---- exp pass -> fp16 P pairs + partial sums; rescale O ----
        float mr = mrow[sr];
        float ps = 0.f;
        #pragma unroll
        for (int c = seg*16; c < seg*16+16; c += 2) {
            float p0 = __expf(St[c*68 + sr] - mr);
            float p1 = __expf(St[(c+1)*68 + sr] - mr);
            Ph[(c >> 1)*72 + sr] = pack_h2(p0, p1);
            ps += p0 + p1;
        }
        red[seg*64 + sr] = ps;
        #pragma unroll
        for (int mi = 0; mi < 2; mi++) {
            int r1 = mw*32 + mi*16 + g;
            float s0 = srow[r1], s1 = srow[r1+8];
            #pragma unroll
            for (int ni = 0; ni < 4; ni++) {
                co[mi][ni][0] *= s0; co[mi][ni][1] *= s0;
                co[mi][ni][2] *= s1; co[mi][ni][3] *= s1;
            }
        }
        __syncthreads();
        if (tid < 64)
            lrow[tid] = lrow[tid]*srow[tid] + red[tid]+red[64+tid]+red[128+tid]+red[192+tid];

        // ---- O += P @ V (fp16, k16 steps over 64 keys) ----
        #pragma unroll
        for (int kb = 0; kb < 4; kb++) {
            uint32_t af[2][4], bf[4][2];
            #pragma unroll
            for (int mi = 0; mi < 2; mi++) {
                int m0 = mw*32 + mi*16;
                af[mi][0] = Ph[(kb*8 + t)*72     + m0 + g];
                af[mi][1] = Ph[(kb*8 + t)*72     + m0 + g + 8];
                af[mi][2] = Ph[(kb*8 + t + 4)*72 + m0 + g];
                af[mi][3] = Ph[(kb*8 + t + 4)*72 + m0 + g + 8];
            }
            #pragma unroll
            for (int ni = 0; ni < 4; ni++) {
                const uint32_t* vp = &Vt[(nw*32 + ni*8 + g)*36 + kb*8 + t];
                bf[ni][0] = vp[0]; bf[ni][1] = vp[4];
            }
            #pragma unroll
            for (int mi = 0; mi < 2; mi++)
                #pragma unroll
                for (int ni = 0; ni < 4; ni++)
                    mma16(co[mi][ni], af[mi], bf[ni]);
        }
        __syncthreads();
    }

    // finalize: divide by l, write fp16 ctx [B, L, H]
    const int b = bh >> 5, h = bh & 31;
    #pragma unroll
    for (int mi = 0; mi < 2; mi++)
        #pragma unroll
        for (int e2 = 0; e2 < 2; e2++) {
            int r = mw*32 + mi*16 + g + e2*8;
            float inv = 1.f / lrow[r];
            __half* drow = g_ch + ((size_t)(b*SEQ) + q0 + r)*HID + h*HD;
            #pragma unroll
            for (int ni = 0; ni < 4; ni++) {
                int d0 = nw*32 + ni*8 + 2*t;
                *(uint32_t*)(drow + d0) =
                    pack_h2(co[mi][ni][e2*2]*inv, co[mi][ni][e2*2+1]*inv);
            }
        }
}

// ---------------- launch ----------------
extern "C" void kernel_launch(void* const* d_in, const int* in_sizes, int n_in,
                              void* d_out, int out_size) {
    const float* x   = (const float*)d_in[0];
    const int*   tt  = (const int*)d_in[1];
    const int*   pos = (const int*)d_in[2];
    /* d_in[3] attention_mask: all zeros, unused (matches reference math) */
    const float* wvq = (const float*)d_in[4];
    const float* wlq = (const float*)d_in[5];
    const float* wvd = (const float*)d_in[6];
    const float* wld = (const float*)d_in[7];
    float* out = (float*)d_out;

    route_kernel<<<1, 1024>>>(tt);

    const int nw4 = (QKV_N*HID)/4;
    const int nd4 = (HID*HID)/4;
    const int nx4 = (TOK*HID)/4;
    cvt_w_kernel<<<(nw4 + 255)/256, 256>>>(wvq, OFF_VQ, nw4);
    cvt_w_kernel<<<(nw4 + 255)/256, 256>>>(wlq, OFF_LQ, nw4);
    cvt_w_kernel<<<(nd4 + 255)/256, 256>>>(wvd, OFF_VD, nd4);
    cvt_w_kernel<<<(nd4 + 255)/256, 256>>>(wld, OFF_LD, nd4);
    cvt_x_kernel<<<(nx4 + 255)/256, 256>>>(x, nx4);

    hgemm<<<dim3(QKV_N/128, 2*TOK/128), 256>>>(nullptr, 0);

    rope_kernel<<<(BSZ*NH*SEQ*32 + 255)/256, 256>>>(pos);
    vtrans_kernel<<<dim3(HD/32, SEQ/32, BSZ*NH), dim3(32, 8)>>>();

    const int attn_smem = 20416 * 4;   // 81664 B
    cudaFuncSetAttribute(attn_kernel, cudaFuncAttributeMaxDynamicSharedMemorySize, attn_smem);
    attn_kernel<<<dim3(SEQ/64, BSZ*NH), 256, attn_smem>>>();

    hgemm<<<dim3(HID/128, 2*TOK/128), 256>>>(out, 1);
}

// round 7
// speedup vs baseline: 5.8928x; 1.1532x over previous
#include <cuda_runtime.h>
#include <cuda_fp16.h>
#include <math_constants.h>
#include <math.h>
#include <stdint.h>

#define HID   4096
#define NH    32
#define HD    128
#define BSZ   2
#define SEQ   2048
#define TOK   (BSZ*SEQ)      /* 4096 */
#define QKV_N (3*HID)        /* 12288 */

// ---------------- device scratch (static, allocation-free) ----------------
__device__ int    g_idx[2*TOK];                       // routed slots, -1 = empty
__device__ float  g_q[(size_t)BSZ*NH*SEQ*HD];         // [B,NH,L,HD] fp32 (pre-RoPE)
__device__ float  g_k[(size_t)BSZ*NH*SEQ*HD];
__device__ float  g_v[(size_t)BSZ*NH*SEQ*HD];

// fp16 operand copies
#define OFF_VQ  ((size_t)0)
#define OFF_LQ  ((size_t)QKV_N*HID)
#define OFF_VD  ((size_t)2*QKV_N*HID)
#define OFF_LD  ((size_t)2*QKV_N*HID + (size_t)HID*HID)
#define W_TOT   ((size_t)2*QKV_N*HID + (size_t)2*HID*HID)
__device__ __half g_wh[W_TOT];                        // all 4 weight matrices, fp16
__device__ __half g_xh[(size_t)TOK*HID];              // input hidden, fp16
__device__ __half g_ch[(size_t)TOK*HID];              // attention context, fp16
__device__ __half g_qh[(size_t)BSZ*NH*SEQ*HD];        // RoPE'd + scaled Q, fp16
__device__ __half g_kh[(size_t)BSZ*NH*SEQ*HD];        // RoPE'd K, fp16
__device__ __half g_vth[(size_t)BSZ*NH*HD*SEQ];       // V transposed [B,NH,HD,SEQ], fp16

// ---------------- helpers ----------------
__device__ __forceinline__ uint32_t pack_h2(float x, float y) {
    __half2 h = __floats2half2_rn(x, y);
    return *reinterpret_cast<uint32_t*>(&h);
}
__device__ __forceinline__ void mma16(float c[4], const uint32_t a[4], const uint32_t b[2]) {
    asm volatile(
        "mma.sync.aligned.m16n8k16.row.col.f32.f16.f16.f32 "
        "{%0,%1,%2,%3},{%4,%5,%6,%7},{%8,%9},{%0,%1,%2,%3};"
        : "+f"(c[0]), "+f"(c[1]), "+f"(c[2]), "+f"(c[3])
        : "r"(a[0]), "r"(a[1]), "r"(a[2]), "r"(a[3]), "r"(b[0]), "r"(b[1]));
}
__device__ __forceinline__ void ldsm4(uint32_t* r, uint32_t a) {
    asm volatile("ldmatrix.sync.aligned.m8n8.x4.shared.b16 {%0,%1,%2,%3}, [%4];"
        : "=r"(r[0]), "=r"(r[1]), "=r"(r[2]), "=r"(r[3]) : "r"(a));
}
__device__ __forceinline__ uint32_t smem_u32(const void* p) {
    uint32_t a;
    asm("{ .reg .u64 t; cvta.to.shared.u64 t, %1; cvt.u32.u64 %0, t; }" : "=r"(a) : "l"(p));
    return a;
}

// ---------------- kernel 1: routing ----------------
__global__ void route_kernel(const int* __restrict__ tt) {
    __shared__ int cnt[2];
    int tid = threadIdx.x;
    if (tid < 2) cnt[tid] = 0;
    for (int i = tid; i < 2*TOK; i += blockDim.x) g_idx[i] = -1;
    __syncthreads();
    for (int t = tid; t < TOK; t += blockDim.x) {
        int l = t & (SEQ-1);
        int vm = (l < SEQ-1) && (tt[t] == 1) && (tt[t+1] == 1);
        int p = atomicAdd(&cnt[vm ? 0 : 1], 1);
        g_idx[(vm ? 0 : TOK) + p] = t;
    }
}

// ---------------- fp16 conversion kernels ----------------
__global__ void cvt_w_kernel(const float* __restrict__ src, size_t off, int n4) {
    int i = blockIdx.x * blockDim.x + threadIdx.x;
    if (i >= n4) return;
    float4 v = ((const float4*)src)[i];
    ((uint2*)(g_wh + off))[i] = make_uint2(pack_h2(v.x, v.y), pack_h2(v.z, v.w));
}
__global__ void cvt_x_kernel(const float* __restrict__ src, int n4) {
    int i = blockIdx.x * blockDim.x + threadIdx.x;
    if (i >= n4) return;
    float4 v = ((const float4*)src)[i];
    ((uint2*)g_xh)[i] = make_uint2(pack_h2(v.x, v.y), pack_h2(v.z, v.w));
}

// ---------------- kernel 2/5: routed GEMM (fp16 HMMA, ldmatrix, dbl-buffer) ----------------
// C[slot, o] = sum_h X[tok(slot), h] * W[o, h]
// Tile 128x128, K-chunk 64, 2 smem stages. 8 warps (2m x 4n), warp tile 64x32.
// mode 0: X = g_xh, scatter -> g_q/g_k/g_v (grid.x = 96); mode 1: X = g_ch -> out.
#define KC     64
#define NC     (HID/KC)            /* 64 chunks */
#define ROWU   36                  /* u32 per smem row (32 data + 4 pad) */
#define A_U32  (128*ROWU)          /* 4608 */
#define STG_U  (2*A_U32)           /* 9216 u32 per stage (A+B) */

__global__ __launch_bounds__(256) void hgemm(float* __restrict__ out, int mode) {
    extern __shared__ __align__(16) uint32_t dsm[];    // 2 stages * 9216 u32 = 73728 B
    __shared__ int stok[128];
    const int tid = threadIdx.x;
    const int rt  = blockIdx.y;                        // <32 => vision

    int myv = 0;
    if (tid < 128) {
        int t = g_idx[rt*128 + tid];
        stok[tid] = t;
        myv = (t >= 0);
    }
    if (!__syncthreads_or(myv)) return;

    const size_t woff = (mode == 0)
        ? (rt < (TOK/128) ? OFF_VQ : OFF_LQ)
        : (rt < (TOK/128) ? OFF_VD : OFF_LD);
    const int obase = blockIdx.x * 128;

    // producer mapping: row = tid>>1 (0..127), q = tid&1 selects 32-half half-row
    const int prow = tid >> 1, q = tid & 1;
    const int tokr = stok[prow];
    const __half* __restrict__ Xh = (mode == 0) ? g_xh : g_ch;
    const __half* __restrict__ xrow = Xh + (size_t)(tokr < 0 ? 0 : tokr) * HID + q*32;
    const __half* __restrict__ wrow = g_wh + woff + (size_t)(obase + prow) * HID + q*32;

    const int w = tid >> 5, lane = tid & 31;
    const int mw = w >> 2, nw = w & 3;
    const int g = lane >> 2, t = lane & 3;
    const int rw = lane & 7, mat = lane >> 3;

    // ldmatrix lane base addresses (bytes)
    const uint32_t smb = smem_u32(dsm);
    uint32_t aBase[4], bBase[2];
    #pragma unroll
    for (int mi = 0; mi < 4; mi++) {
        int row = mw*64 + mi*16 + (mat & 1)*8 + rw;
        aBase[mi] = smb + row*(ROWU*4) + (mat >> 1)*16;
    }
    #pragma unroll
    for (int p = 0; p < 2; p++) {
        int row = nw*32 + p*16 + (mat >> 1)*8 + rw;
        bBase[p] = smb + A_U32*4 + row*(ROWU*4) + (mat & 1)*16;
    }

    float c[4][4][4];
    #pragma unroll
    for (int mi = 0; mi < 4; mi++)
        #pragma unroll
        for (int ni = 0; ni < 4; ni++)
            #pragma unroll
            for (int e = 0; e < 4; e++) c[mi][ni][e] = 0.f;

    uint4 pa[4], pb[4];
    // prologue: chunk 0 -> regs -> stage 0; chunk 1 -> regs
    #pragma unroll
    for (int j = 0; j < 4; j++) {
        pa[j] = (tokr >= 0) ? *(const uint4*)(xrow + j*8) : make_uint4(0,0,0,0);
        pb[j] = *(const uint4*)(wrow + j*8);
    }
    {
        uint32_t* As = dsm + prow*ROWU + q*16;
        uint32_t* Bs = dsm + A_U32 + prow*ROWU + q*16;
        #pragma unroll
        for (int j = 0; j < 4; j++) {
            *(uint2*)(As + j*4)     = make_uint2(pa[j].x, pa[j].y);
            *(uint2*)(As + j*4 + 2) = make_uint2(pa[j].z, pa[j].w);
            *(uint2*)(Bs + j*4)     = make_uint2(pb[j].x, pb[j].y);
            *(uint2*)(Bs + j*4 + 2) = make_uint2(pb[j].z, pb[j].w);
        }
    }
    #pragma unroll
    for (int j = 0; j < 4; j++) {
        pa[j] = (tokr >= 0) ? *(const uint4*)(xrow + KC + j*8) : make_uint4(0,0,0,0);
        pb[j] = *(const uint4*)(wrow + KC + j*8);
    }
    __syncthreads();

    for (int cI = 0; cI < NC; cI++) {
        const int s = cI & 1;
        if (cI + 1 < NC) {
            // store prefetched chunk cI+1 into stage s^1 (free since last sync)
            uint32_t* As = dsm + (s^1)*STG_U + prow*ROWU + q*16;
            uint32_t* Bs = As + A_U32;
            #pragma unroll
            for (int j = 0; j < 4; j++) {
                *(uint2*)(As + j*4)     = make_uint2(pa[j].x, pa[j].y);
                *(uint2*)(As + j*4 + 2) = make_uint2(pa[j].z, pa[j].w);
                *(uint2*)(Bs + j*4)     = make_uint2(pb[j].x, pb[j].y);
                *(uint2*)(Bs + j*4 + 2) = make_uint2(pb[j].z, pb[j].w);
            }
            if (cI + 2 < NC) {
                const size_t ke = (size_t)(cI + 2) * KC;
                #pragma unroll
                for (int j = 0; j < 4; j++) {
                    pa[j] = (tokr >= 0) ? *(const uint4*)(xrow + ke + j*8) : make_uint4(0,0,0,0);
                    pb[j] = *(const uint4*)(wrow + ke + j*8);
                }
            }
        }
        // compute on stage s: 4 k16 steps
        const uint32_t so = s * (STG_U*4);
        #pragma unroll
        for (int kb = 0; kb < 4; kb++) {
            uint32_t af[4][4], bf[4][2];
            #pragma unroll
            for (int mi = 0; mi < 4; mi++)
                ldsm4(af[mi], aBase[mi] + so + kb*32);
            #pragma unroll
            for (int p = 0; p < 2; p++) {
                uint32_t rr[4];
                ldsm4(rr, bBase[p] + so + kb*32);
                bf[2*p][0] = rr[0]; bf[2*p][1] = rr[1];
                bf[2*p+1][0] = rr[2]; bf[2*p+1][1] = rr[3];
            }
            #pragma unroll
            for (int mi = 0; mi < 4; mi++)
                #pragma unroll
                for (int ni = 0; ni < 4; ni++)
                    mma16(c[mi][ni], af[mi], bf[ni]);
        }
        __syncthreads();
    }

    if (mode == 0) {
        const int part = blockIdx.x >> 5;
        const int head = blockIdx.x & 31;
        float* dst = (part == 0) ? g_q : (part == 1) ? g_k : g_v;
        #pragma unroll
        for (int mi = 0; mi < 4; mi++)
            #pragma unroll
            for (int e2 = 0; e2 < 2; e2++) {
                int m = mw*64 + mi*16 + g + e2*8;
                int tk = stok[m];
                if (tk < 0) continue;
                int b = tk >> 11, l = tk & (SEQ-1);
                float* drow = dst + (((size_t)(b*NH + head))*SEQ + l)*HD;
                #pragma unroll
                for (int ni = 0; ni < 4; ni++) {
                    int d0 = nw*32 + ni*8 + 2*t;
                    *(float2*)(drow + d0) = make_float2(c[mi][ni][e2*2], c[mi][ni][e2*2+1]);
                }
            }
    } else {
        #pragma unroll
        for (int mi = 0; mi < 4; mi++)
            #pragma unroll
            for (int e2 = 0; e2 < 2; e2++) {
                int m = mw*64 + mi*16 + g + e2*8;
                int tk = stok[m];
                if (tk < 0) continue;
                float* drow = out + (size_t)tk*HID + obase;
                #pragma unroll
                for (int ni = 0; ni < 4; ni++) {
                    int d0 = nw*32 + ni*8 + 2*t;
                    *(float2*)(drow + d0) = make_float2(c[mi][ni][e2*2], c[mi][ni][e2*2+1]);
                }
            }
    }
}

// ---------------- kernel 3: RoPE -> fp16 Q (scaled), K ----------------
__global__ void rope_kernel(const int* __restrict__ pos_ids) {
    int i = blockIdx.x * blockDim.x + threadIdx.x;     // B*NH*SEQ*32
    if (i >= BSZ*NH*SEQ*32) return;
    int j = i & 31;
    int l = (i >> 5) & (SEQ-1);
    int h = (i >> 16) & (NH-1);
    int b = i >> 21;
    int pos = pos_ids[(b << 11) | l];
    float f0 = powf(10000.f, -(float)(2*j)   * (1.f/64.f));
    float f1 = powf(10000.f, -(float)(2*j+1) * (1.f/64.f));
    float s0, c0, s1, c1;
    sincosf((float)pos * f0, &s0, &c0);
    sincosf((float)pos * f1, &s1, &c1);
    const size_t base = (((size_t)(b*NH + h))*SEQ + l)*HD;
    const float qs = 0.08838834764831845f;

    float2 qa = *(const float2*)(g_q + base + 2*j);
    float2 qb = *(const float2*)(g_q + base + 2*j + 64);
    *(uint32_t*)(g_qh + base + 2*j)      = pack_h2((qa.x*c0 - qb.x*s0)*qs, (qa.y*c1 - qb.y*s1)*qs);
    *(uint32_t*)(g_qh + base + 2*j + 64) = pack_h2((qb.x*c0 + qa.x*s0)*qs, (qb.y*c1 + qa.y*s1)*qs);

    float2 ka = *(const float2*)(g_k + base + 2*j);
    float2 kb = *(const float2*)(g_k + base + 2*j + 64);
    *(uint32_t*)(g_kh + base + 2*j)      = pack_h2(ka.x*c0 - kb.x*s0, ka.y*c1 - kb.y*s1);
    *(uint32_t*)(g_kh + base + 2*j + 64) = pack_h2(kb.x*c0 + ka.x*s0, kb.y*c1 + ka.y*s1);
}

// ---------------- kernel 3b: V transpose -> fp16 [B,NH,HD,SEQ] ----------------
__global__ void vtrans_kernel() {
    __shared__ float ts[32][33];
    const int bh = blockIdx.z;
    const int l0 = blockIdx.y * 32, d0 = blockIdx.x * 32;
    const int tx = threadIdx.x, ty = threadIdx.y;       // (32,8)
    const float* __restrict__ src = g_v + ((size_t)bh*SEQ + l0)*HD + d0;
    #pragma unroll
    for (int k = 0; k < 4; k++)
        ts[ty + 8*k][tx] = src[(size_t)(ty + 8*k)*HD + tx];
    __syncthreads();
    __half* dst = g_vth + ((size_t)bh*HD + d0)*SEQ + l0;
    #pragma unroll
    for (int k = 0; k < 4; k++)
        dst[(size_t)(ty + 8*k)*SEQ + tx] = __float2half(ts[tx][ty + 8*k]);
}

// ---------------- kernel 4: flash attention (fp16 HMMA, 2 CTA/SM) ----------------
__global__ __launch_bounds__(256, 2) void attn_kernel() {
    extern __shared__ __align__(16) uint32_t smu[];
    uint32_t* Qs = smu;                    // [64][68] u32
    uint32_t* Ks = smu + 4352;             // [64][68]
    uint32_t* Vt = smu + 8704;             // [128][36]
    uint32_t* Ph = smu + 13312;            // [32][72]
    float*    St = (float*)(smu + 15616);  // [64][68] fp32, [key][query]
    float*  mrow = (float*)(smu + 19968);
    float*  lrow = mrow + 64;
    float*  srow = lrow + 64;
    float*  red  = srow + 64;

    const int tid = threadIdx.x;
    const int bh  = blockIdx.y;
    const int q0  = blockIdx.x * 64;
    const __half* __restrict__ Qg = g_qh  + (size_t)bh * SEQ * HD;
    const __half* __restrict__ Kg = g_kh  + (size_t)bh * SEQ * HD;
    const __half* __restrict__ Vg = g_vth + (size_t)bh * HD * SEQ;
    const int w = tid >> 5, lane = tid & 31;
    const int g = lane >> 2, t = lane & 3;
    const int mw = w >> 2, nw = w & 3;

    for (int r = w; r < 64; r += 8) {
        uint2 qv = *(const uint2*)(Qg + (size_t)(q0+r)*HD + lane*4);
        Qs[r*68 + lane*2]     = qv.x;
        Qs[r*68 + lane*2 + 1] = qv.y;
    }
    if (tid < 64) { mrow[tid] = -CUDART_INF_F; lrow[tid] = 0.f; }

    const int sr = tid & 63, seg = tid >> 6;
    float co[2][4][4];
    #pragma unroll
    for (int mi = 0; mi < 2; mi++)
        #pragma unroll
        for (int ni = 0; ni < 4; ni++)
            #pragma unroll
            for (int e = 0; e < 4; e++) co[mi][ni][e] = 0.f;
    __syncthreads();

    for (int kt = 0; kt < SEQ/64; kt++) {
        const int k0 = kt * 64;
        for (int r = w; r < 64; r += 8) {
            uint2 kv = *(const uint2*)(Kg + (size_t)(k0+r)*HD + lane*4);
            Ks[r*68 + lane*2]     = kv.x;
            Ks[r*68 + lane*2 + 1] = kv.y;
        }
        #pragma unroll
        for (int it = 0; it < 4; it++) {
            int chunk = tid + it*256;
            int row = chunk >> 3, c4 = chunk & 7;
            uint4 vv = *(const uint4*)(Vg + (size_t)row*SEQ + k0 + c4*8);
            *(uint4*)&Vt[row*36 + c4*4] = vv;
        }
        __syncthreads();

        float cs[2][2][4];
        #pragma unroll
        for (int mi = 0; mi < 2; mi++)
            #pragma unroll
            for (int ni = 0; ni < 2; ni++)
                #pragma unroll
                for (int e = 0; e < 4; e++) cs[mi][ni][e] = 0.f;
        #pragma unroll
        for (int kb = 0; kb < 8; kb++) {
            uint32_t af[2][4], bf[2][2];
            #pragma unroll
            for (int mi = 0; mi < 2; mi++) {
                const uint32_t* ap = &Qs[(mw*32 + mi*16 + g)*68 + kb*8 + t];
                af[mi][0] = ap[0]; af[mi][1] = ap[8*68];
                af[mi][2] = ap[4]; af[mi][3] = ap[8*68 + 4];
            }
            #pragma unroll
            for (int ni = 0; ni < 2; ni++) {
                const uint32_t* bp = &Ks[(nw*16 + ni*8 + g)*68 + kb*8 + t];
                bf[ni][0] = bp[0]; bf[ni][1] = bp[4];
            }
            #pragma unroll
            for (int mi = 0; mi < 2; mi++)
                #pragma unroll
                for (int ni = 0; ni < 2; ni++)
                    mma16(cs[mi][ni], af[mi], bf[ni]);
        }
        #pragma unroll
        for (int mi = 0; mi < 2; mi++)
            #pragma unroll
            for (int ni = 0; ni < 2; ni++)
                #pragma unroll
                for (int e = 0; e < 4; e++) {
                    int rr = mw*32 + mi*16 + g + (e >> 1)*8;
                    int cc = nw*16 + ni*8 + 2*t + (e & 1);
                    St[cc*68 + rr] = cs[mi][ni][e];
                }
        __syncthreads();

        float pm = -CUDART_INF_F;
        #pragma unroll
        for (int c = seg*16; c < seg*16+16; c++) pm = fmaxf(pm, St[c*68 + sr]);
        red[seg*64 + sr] = pm;
        __syncthreads();
        if (tid < 64) {
            float mo = mrow[tid];
            float mn = fmaxf(fmaxf(red[tid], red[64+tid]), fmaxf(red[128+tid], red[192+tid]));
            mn = fmaxf(mo, mn);
            mrow[tid] = mn;
            srow[tid] = __expf(mo - mn);
        }
        __syncthreads();

        float mr = mrow[sr];
        float ps = 0.f;
        #pragma unroll
        for (int c = seg*16; c < seg*16+16; c += 2) {
            float p0 = __expf(St[c*68 + sr] - mr);
            float p1 = __expf(St[(c+1)*68 + sr] - mr);
            Ph[(c >> 1)*72 + sr] = pack_h2(p0, p1);
            ps += p0 + p1;
        }
        red[seg*64 + sr] = ps;
        #pragma unroll
        for (int mi = 0; mi < 2; mi++) {
            int r1 = mw*32 + mi*16 + g;
            float s0 = srow[r1], s1 = srow[r1+8];
            #pragma unroll
            for (int ni = 0; ni < 4; ni++) {
                co[mi][ni][0] *= s0; co[mi][ni][1] *= s0;
                co[mi][ni][2] *= s1; co[mi][ni][3] *= s1;
            }
        }
        __syncthreads();
        if (tid < 64)
            lrow[tid] = lrow[tid]*srow[tid] + red[tid]+red[64+tid]+red[128+tid]+red[192+tid];

        #pragma unroll
        for (int kb = 0; kb < 4; kb++) {
            uint32_t af[2][4], bf[4][2];
            #pragma unroll
            for (int mi = 0; mi < 2; mi++) {
                int m0 = mw*32 + mi*16;
                af[mi][0] = Ph[(kb*8 + t)*72     + m0 + g];
                af[mi][1] = Ph[(kb*8 + t)*72     + m0 + g + 8];
                af[mi][2] = Ph[(kb*8 + t + 4)*72 + m0 + g];
                af[mi][3] = Ph[(kb*8 + t + 4)*72 + m0 + g + 8];
            }
            #pragma unroll
            for (int ni = 0; ni < 4; ni++) {
                const uint32_t* vp = &Vt[(nw*32 + ni*8 + g)*36 + kb*8 + t];
                bf[ni][0] = vp[0]; bf[ni][1] = vp[4];
            }
            #pragma unroll
            for (int mi = 0; mi < 2; mi++)
                #pragma unroll
                for (int ni = 0; ni < 4; ni++)
                    mma16(co[mi][ni], af[mi], bf[ni]);
        }
        __syncthreads();
    }

    const int b = bh >> 5, h = bh & 31;
    #pragma unroll
    for (int mi = 0; mi < 2; mi++)
        #pragma unroll
        for (int e2 = 0; e2 < 2; e2++) {
            int r = mw*32 + mi*16 + g + e2*8;
            float inv = 1.f / lrow[r];
            __half* drow = g_ch + ((size_t)(b*SEQ) + q0 + r)*HID + h*HD;
            #pragma unroll
            for (int ni = 0; ni < 4; ni++) {
                int d0 = nw*32 + ni*8 + 2*t;
                *(uint32_t*)(drow + d0) =
                    pack_h2(co[mi][ni][e2*2]*inv, co[mi][ni][e2*2+1]*inv);
            }
        }
}

// ---------------- launch ----------------
extern "C" void kernel_launch(void* const* d_in, const int* in_sizes, int n_in,
                              void* d_out, int out_size) {
    const float* x   = (const float*)d_in[0];
    const int*   tt  = (const int*)d_in[1];
    const int*   pos = (const int*)d_in[2];
    /* d_in[3] attention_mask: all zeros, unused (matches reference math) */
    const float* wvq = (const float*)d_in[4];
    const float* wlq = (const float*)d_in[5];
    const float* wvd = (const float*)d_in[6];
    const float* wld = (const float*)d_in[7];
    float* out = (float*)d_out;

    route_kernel<<<1, 1024>>>(tt);

    const int nw4 = (QKV_N*HID)/4;
    const int nd4 = (HID*HID)/4;
    const int nx4 = (TOK*HID)/4;
    cvt_w_kernel<<<(nw4 + 255)/256, 256>>>(wvq, OFF_VQ, nw4);
    cvt_w_kernel<<<(nw4 + 255)/256, 256>>>(wlq, OFF_LQ, nw4);
    cvt_w_kernel<<<(nd4 + 255)/256, 256>>>(wvd, OFF_VD, nd4);
    cvt_w_kernel<<<(nd4 + 255)/256, 256>>>(wld, OFF_LD, nd4);
    cvt_x_kernel<<<(nx4 + 255)/256, 256>>>(x, nx4);

    const int gemm_smem = 2 * STG_U * 4;   // 73728 B
    cudaFuncSetAttribute(hgemm, cudaFuncAttributeMaxDynamicSharedMemorySize, gemm_smem);
    hgemm<<<dim3(QKV_N/128, 2*TOK/128), 256, gemm_smem>>>(nullptr, 0);

    rope_kernel<<<(BSZ*NH*SEQ*32 + 255)/256, 256>>>(pos);
    vtrans_kernel<<<dim3(HD/32, SEQ/32, BSZ*NH), dim3(32, 8)>>>();

    const int attn_smem = 20416 * 4;   // 81664 B
    cudaFuncSetAttribute(attn_kernel, cudaFuncAttributeMaxDynamicSharedMemorySize, attn_smem);
    attn_kernel<<<dim3(SEQ/64, BSZ*NH), 256, attn_smem>>>();

    hgemm<<<dim3(HID/128, 2*TOK/128), 256, gemm_smem>>>(out, 1);
}